// round 9
// baseline (speedup 1.0000x reference)
#include <cuda_runtime.h>
#include <math.h>

#define D_MODEL 1024
#define NHEADS  16
#define DK      64
#define BATCH   2
#define SEQ     2048
#define HEAD_ELEMS (BATCH * NHEADS * SEQ * DK)   // 4,194,304 floats (16 MB)

// Scratch: __device__ globals (allocation guards forbid cudaMalloc)
__device__ float g_Qh[HEAD_ELEMS];
__device__ float g_Kh[HEAD_ELEMS];
__device__ float g_Vh[HEAD_ELEMS];
__device__ float g_ctx[HEAD_ELEMS];

// ---------------------------------------------------------------------------
// Kernel 1: fused QKV head projections.
//   Qh[b,h,t,k] = sum_d X[b,t,d] * W[h,d,k] + bias[h,k]
// Treated as GEMM M=B*T=4096, N=H*DK=1024, K=D_MODEL=1024.
// W is head-blocked: element (d, n) lives at W[(n>>6)*D_MODEL*DK + d*DK + (n&63)].
// blockIdx.z selects Q / K / V.
// Tile 128x128x8, 256 threads, 8x8 microtile, register prefetch of next k-slice.
// ---------------------------------------------------------------------------
__global__ __launch_bounds__(256)
void proj_kernel(const float* __restrict__ Qin, const float* __restrict__ Kin,
                 const float* __restrict__ Vin,
                 const float* __restrict__ Wq, const float* __restrict__ Wk,
                 const float* __restrict__ Wv,
                 const float* __restrict__ bq, const float* __restrict__ bk,
                 const float* __restrict__ bv)
{
    const float* A;
    const float* W;
    const float* bias;
    float* C;
    if (blockIdx.z == 0)      { A = Qin; W = Wq; bias = bq; C = g_Qh; }
    else if (blockIdx.z == 1) { A = Kin; W = Wk; bias = bk; C = g_Kh; }
    else                      { A = Vin; W = Wv; bias = bv; C = g_Vh; }

    __shared__ __align__(16) float As[8][128];
    __shared__ __align__(16) float Bs[8][128];

    const int tid  = threadIdx.x;
    const int m0   = blockIdx.y * 128;
    const int n0   = blockIdx.x * 128;
    const int arow = tid >> 1;            // 0..127
    const int acol = (tid & 1) * 4;       // 0 / 4
    const int brow = tid >> 5;            // 0..7
    const int bcol = (tid & 31) * 4;      // 0..124
    const int tx   = tid & 15;
    const int ty   = tid >> 4;

    float acc[8][8];
#pragma unroll
    for (int i = 0; i < 8; i++)
#pragma unroll
        for (int j = 0; j < 8; j++) acc[i][j] = 0.0f;

    const float* Aptr = A + (size_t)(m0 + arow) * D_MODEL + acol;
    const int    nB   = n0 + bcol;
    const float* Wptr = W + (size_t)(nB >> 6) * (D_MODEL * DK) + (nB & 63);

    float4 aReg = *(const float4*)(Aptr);
    float4 bReg = *(const float4*)(Wptr + brow * DK);

    for (int k0 = 0; k0 < D_MODEL; k0 += 8) {
        __syncthreads();
        As[acol + 0][arow] = aReg.x;
        As[acol + 1][arow] = aReg.y;
        As[acol + 2][arow] = aReg.z;
        As[acol + 3][arow] = aReg.w;
        *(float4*)&Bs[brow][bcol] = bReg;
        __syncthreads();

        if (k0 + 8 < D_MODEL) {  // prefetch next slice (overlaps with compute)
            aReg = *(const float4*)(Aptr + k0 + 8);
            bReg = *(const float4*)(Wptr + (size_t)(k0 + 8 + brow) * DK);
        }

#pragma unroll
        for (int kk = 0; kk < 8; kk++) {
            float af[8], bf[8];
#pragma unroll
            for (int i = 0; i < 8; i++) af[i] = As[kk][ty * 8 + i];
#pragma unroll
            for (int j = 0; j < 8; j++) bf[j] = Bs[kk][tx * 8 + j];
#pragma unroll
            for (int i = 0; i < 8; i++)
#pragma unroll
                for (int j = 0; j < 8; j++)
                    acc[i][j] = fmaf(af[i], bf[j], acc[i][j]);
        }
    }

    // Epilogue: scatter into [B,H,T,DK] layout, add bias (bias flat = [H*DK])
#pragma unroll
    for (int i = 0; i < 8; i++) {
        const int m = m0 + ty * 8 + i;
        const int b = m >> 11;
        const int t = m & (SEQ - 1);
#pragma unroll
        for (int j = 0; j < 8; j++) {
            const int n = n0 + tx * 8 + j;
            const int h = n >> 6;
            const int k = n & 63;
            C[(((size_t)(b * NHEADS + h)) * SEQ + t) * DK + k] = acc[i][j] + bias[n];
        }
    }
}

// ---------------------------------------------------------------------------
// Kernel 2: flash attention per (b,h).
// Block: 128 queries x full key loop (tiles of 64). 256 threads, microtile 8x4.
// Online softmax (exact), P staged through SMEM for the PV GEMM.
// ---------------------------------------------------------------------------
__global__ __launch_bounds__(256, 2)
void attn_kernel()
{
    extern __shared__ float sm[];
    float* Qs = sm;                       // [128][65]
    float* Ks = Qs + 128 * 65;            // [64][65]
    float* Vs = Ks + 64 * 65;             // [64][64]  (unpadded: float4-aligned rows)
    float* Ps = Vs + 64 * 64;             // [128][65]

    const int bh = blockIdx.y;            // 0..B*H-1
    const int q0 = blockIdx.x * 128;
    const float* Qbase = g_Qh + (size_t)bh * SEQ * DK;
    const float* Kbase = g_Kh + (size_t)bh * SEQ * DK;
    const float* Vbase = g_Vh + (size_t)bh * SEQ * DK;
    float*       Cbase = g_ctx + (size_t)bh * SEQ * DK;

    const int tid = threadIdx.x;
    const int tx  = tid & 15;             // key/dk column group (4 cols)
    const int ty  = tid >> 4;             // query row group (8 rows)
    const float scale = 0.125f;           // 1/sqrt(64)

    // Load Q tile (128x64) once
#pragma unroll
    for (int i = 0; i < 8; i++) {
        const int idx = tid + i * 256;
        const int r   = idx >> 4;
        const int c   = (idx & 15) * 4;
        float4 v = *(const float4*)(Qbase + (size_t)(q0 + r) * DK + c);
        Qs[r * 65 + c + 0] = v.x;
        Qs[r * 65 + c + 1] = v.y;
        Qs[r * 65 + c + 2] = v.z;
        Qs[r * 65 + c + 3] = v.w;
    }

    float m_i[8], l_i[8], O[8][4];
#pragma unroll
    for (int i = 0; i < 8; i++) {
        m_i[i] = -1e30f;
        l_i[i] = 0.0f;
#pragma unroll
        for (int j = 0; j < 4; j++) O[i][j] = 0.0f;
    }

    for (int s0 = 0; s0 < SEQ; s0 += 64) {
        __syncthreads();   // previous PV done before overwriting Ks/Vs
        // Load K,V tiles (64x64 each)
#pragma unroll
        for (int i = 0; i < 4; i++) {
            const int idx = tid + i * 256;
            const int r   = idx >> 4;
            const int c   = (idx & 15) * 4;
            float4 kv = *(const float4*)(Kbase + (size_t)(s0 + r) * DK + c);
            Ks[r * 65 + c + 0] = kv.x;
            Ks[r * 65 + c + 1] = kv.y;
            Ks[r * 65 + c + 2] = kv.z;
            Ks[r * 65 + c + 3] = kv.w;
            float4 vv = *(const float4*)(Vbase + (size_t)(s0 + r) * DK + c);
            *(float4*)(Vs + r * 64 + c) = vv;
        }
        __syncthreads();

        // S = Q @ K^T  (128x64 tile, inner dim 64)
        float s_acc[8][4];
#pragma unroll
        for (int i = 0; i < 8; i++)
#pragma unroll
            for (int j = 0; j < 4; j++) s_acc[i][j] = 0.0f;

#pragma unroll 4
        for (int kk = 0; kk < 64; kk++) {
            float a[8], bv[4];
#pragma unroll
            for (int i = 0; i < 8; i++) a[i] = Qs[(ty * 8 + i) * 65 + kk];
#pragma unroll
            for (int j = 0; j < 4; j++) bv[j] = Ks[(tx * 4 + j) * 65 + kk];
#pragma unroll
            for (int i = 0; i < 8; i++)
#pragma unroll
                for (int j = 0; j < 4; j++)
                    s_acc[i][j] = fmaf(a[i], bv[j], s_acc[i][j]);
        }

        // Online softmax per query row (row spread over 16 lanes, same-ty group)
#pragma unroll
        for (int i = 0; i < 8; i++) {
            float mt = -1e30f;
#pragma unroll
            for (int j = 0; j < 4; j++) {
                s_acc[i][j] *= scale;
                mt = fmaxf(mt, s_acc[i][j]);
            }
#pragma unroll
            for (int off = 8; off >= 1; off >>= 1)
                mt = fmaxf(mt, __shfl_xor_sync(0xffffffffu, mt, off));

            const float m_new = fmaxf(m_i[i], mt);
            const float alpha = __expf(m_i[i] - m_new);
            float rs = 0.0f;
#pragma unroll
            for (int j = 0; j < 4; j++) {
                const float p = __expf(s_acc[i][j] - m_new);
                s_acc[i][j] = p;
                rs += p;
            }
#pragma unroll
            for (int off = 8; off >= 1; off >>= 1)
                rs += __shfl_xor_sync(0xffffffffu, rs, off);

            l_i[i] = l_i[i] * alpha + rs;
            m_i[i] = m_new;
#pragma unroll
            for (int j = 0; j < 4; j++) O[i][j] *= alpha;
#pragma unroll
            for (int j = 0; j < 4; j++)
                Ps[(ty * 8 + i) * 65 + tx * 4 + j] = s_acc[i][j];
        }
        __syncthreads();

        // O += P @ V  (128x64 += 128x64 @ 64x64)
#pragma unroll 4
        for (int s = 0; s < 64; s++) {
            float a[8];
#pragma unroll
            for (int i = 0; i < 8; i++) a[i] = Ps[(ty * 8 + i) * 65 + s];
            const float4 vv = *(const float4*)(Vs + s * 64 + tx * 4);
#pragma unroll
            for (int i = 0; i < 8; i++) {
                O[i][0] = fmaf(a[i], vv.x, O[i][0]);
                O[i][1] = fmaf(a[i], vv.y, O[i][1]);
                O[i][2] = fmaf(a[i], vv.z, O[i][2]);
                O[i][3] = fmaf(a[i], vv.w, O[i][3]);
            }
        }
    }

    // Epilogue: normalize, write ctx[b,h,t,k]
#pragma unroll
    for (int i = 0; i < 8; i++) {
        const float inv = 1.0f / l_i[i];
        const int r = q0 + ty * 8 + i;
#pragma unroll
        for (int j = 0; j < 4; j++)
            Cbase[(size_t)r * DK + tx * 4 + j] = O[i][j] * inv;
    }
}

// ---------------------------------------------------------------------------
// Kernel 3: output projection.
//   x = ctx viewed flat [4096, 1024] (matches the reference's transpose-free
//   reshape exactly, since ctx is stored [B,H,T,dk] contiguous).
//   out[m, o] = sum_j x[m, j] * Wo[o, j] + bo[o]        (NT GEMM)
// ---------------------------------------------------------------------------
__global__ __launch_bounds__(256)
void out_kernel(float* __restrict__ Out, const float* __restrict__ Wo,
                const float* __restrict__ bo)
{
    __shared__ __align__(16) float As[8][128];
    __shared__ __align__(16) float Bs[8][128];

    const float* A = g_ctx;
    const int tid  = threadIdx.x;
    const int m0   = blockIdx.y * 128;
    const int n0   = blockIdx.x * 128;
    const int arow = tid >> 1;
    const int acol = (tid & 1) * 4;
    const int wrow = tid >> 1;            // local n index (0..127)
    const int wcol = (tid & 1) * 4;       // k offset (0 / 4)
    const int tx   = tid & 15;
    const int ty   = tid >> 4;

    float acc[8][8];
#pragma unroll
    for (int i = 0; i < 8; i++)
#pragma unroll
        for (int j = 0; j < 8; j++) acc[i][j] = 0.0f;

    const float* Aptr = A + (size_t)(m0 + arow) * D_MODEL + acol;
    const float* Wptr = Wo + (size_t)(n0 + wrow) * D_MODEL + wcol;

    float4 aReg = *(const float4*)(Aptr);
    float4 bReg = *(const float4*)(Wptr);

    for (int k0 = 0; k0 < D_MODEL; k0 += 8) {
        __syncthreads();
        As[acol + 0][arow] = aReg.x;
        As[acol + 1][arow] = aReg.y;
        As[acol + 2][arow] = aReg.z;
        As[acol + 3][arow] = aReg.w;
        Bs[wcol + 0][wrow] = bReg.x;      // transposed store: Bs[k][n_local]
        Bs[wcol + 1][wrow] = bReg.y;
        Bs[wcol + 2][wrow] = bReg.z;
        Bs[wcol + 3][wrow] = bReg.w;
        __syncthreads();

        if (k0 + 8 < D_MODEL) {
            aReg = *(const float4*)(Aptr + k0 + 8);
            bReg = *(const float4*)(Wptr + k0 + 8);
        }

#pragma unroll
        for (int kk = 0; kk < 8; kk++) {
            float af[8], bf[8];
#pragma unroll
            for (int i = 0; i < 8; i++) af[i] = As[kk][ty * 8 + i];
#pragma unroll
            for (int j = 0; j < 8; j++) bf[j] = Bs[kk][tx * 8 + j];
#pragma unroll
            for (int i = 0; i < 8; i++)
#pragma unroll
                for (int j = 0; j < 8; j++)
                    acc[i][j] = fmaf(af[i], bf[j], acc[i][j]);
        }
    }

#pragma unroll
    for (int i = 0; i < 8; i++) {
        const int m = m0 + ty * 8 + i;
#pragma unroll
        for (int j = 0; j < 8; j++) {
            const int n = n0 + tx * 8 + j;
            Out[(size_t)m * D_MODEL + n] = acc[i][j] + bo[n];
        }
    }
}

// ---------------------------------------------------------------------------
extern "C" void kernel_launch(void* const* d_in, const int* in_sizes, int n_in,
                              void* d_out, int out_size)
{
    (void)in_sizes; (void)n_in; (void)out_size;
    const float* Q  = (const float*)d_in[0];
    const float* K  = (const float*)d_in[1];
    const float* V  = (const float*)d_in[2];
    const float* Wq = (const float*)d_in[3];
    const float* bq = (const float*)d_in[4];
    const float* Wk = (const float*)d_in[5];
    const float* bk = (const float*)d_in[6];
    const float* Wv = (const float*)d_in[7];
    const float* bv = (const float*)d_in[8];
    const float* Wo = (const float*)d_in[9];
    const float* bo = (const float*)d_in[10];
    float* Out = (float*)d_out;

    // QKV projections: grid (N/128, M/128, 3)
    proj_kernel<<<dim3(D_MODEL / 128, (BATCH * SEQ) / 128, 3), 256>>>(
        Q, K, V, Wq, Wk, Wv, bq, bk, bv);

    // Flash attention: grid (T/128, B*H), ~99.6 KB dynamic smem
    const int ATTN_SMEM = (128 * 65 + 64 * 65 + 64 * 64 + 128 * 65) * (int)sizeof(float);
    cudaFuncSetAttribute((const void*)attn_kernel,
                         cudaFuncAttributeMaxDynamicSharedMemorySize, ATTN_SMEM);
    attn_kernel<<<dim3(SEQ / 128, BATCH * NHEADS), 256, ATTN_SMEM>>>();

    // Output projection
    out_kernel<<<dim3(D_MODEL / 128, (BATCH * SEQ) / 128), 256>>>(Out, Wo, bo);
}

// round 15
// speedup vs baseline: 1.3102x; 1.3102x over previous
#include <cuda_runtime.h>
#include <cuda_bf16.h>
#include <math.h>
#include <stdint.h>

#define D_MODEL 1024
#define NHEADS  16
#define DK      64
#define BATCH   2
#define SEQ     2048
#define M_TOTAL (BATCH * SEQ)                    // 4096
#define HEAD_ELEMS (BATCH * NHEADS * SEQ * DK)   // 4,194,304 floats

// ---------------- scratch (__device__ globals; allocation guards forbid cudaMalloc)
__device__ float g_Qh[HEAD_ELEMS];
__device__ float g_Kh[HEAD_ELEMS];
__device__ float g_Vh[HEAD_ELEMS];
__device__ float g_ctx[HEAD_ELEMS];

// bf16 hi/lo split operands for tensor-core GEMMs
__device__ __nv_bfloat16 g_Ahi[3ull * M_TOTAL * D_MODEL];
__device__ __nv_bfloat16 g_Alo[3ull * M_TOTAL * D_MODEL];
__device__ __nv_bfloat16 g_Whi[4ull * D_MODEL * D_MODEL];  // [Wq,Wk,Wv,Wo] K-major [n][k]
__device__ __nv_bfloat16 g_Wlo[4ull * D_MODEL * D_MODEL];
__device__ __nv_bfloat16 g_Chi[(size_t)M_TOTAL * D_MODEL];
__device__ __nv_bfloat16 g_Clo[(size_t)M_TOTAL * D_MODEL];

// ---------------- PTX helpers (sm_80-era: valid under compute_103 virtual target)
__device__ __forceinline__ uint32_t smem_to_u32(const void* p) {
    uint32_t a;
    asm("{ .reg .u64 t; cvta.to.shared.u64 t, %1; cvt.u32.u64 %0, t; }" : "=r"(a) : "l"(p));
    return a;
}
#define CP_ASYNC16(smem_addr, gptr) \
    asm volatile("cp.async.cg.shared.global [%0], [%1], 16;" :: "r"((uint32_t)(smem_addr)), "l"(gptr))
#define CP_COMMIT() asm volatile("cp.async.commit_group;" ::: "memory")
#define CP_WAIT1()  asm volatile("cp.async.wait_group 1;" ::: "memory")
#define CP_WAIT0()  asm volatile("cp.async.wait_group 0;" ::: "memory")

__device__ __forceinline__ void ldsm_x4(uint32_t& r0, uint32_t& r1, uint32_t& r2, uint32_t& r3,
                                        uint32_t addr) {
    asm volatile("ldmatrix.sync.aligned.m8n8.x4.shared.b16 {%0,%1,%2,%3}, [%4];"
                 : "=r"(r0), "=r"(r1), "=r"(r2), "=r"(r3) : "r"(addr));
}
__device__ __forceinline__ void mma_16816(float* d, const uint32_t* a, const uint32_t* b) {
    asm volatile(
        "mma.sync.aligned.m16n8k16.row.col.f32.bf16.bf16.f32 "
        "{%0,%1,%2,%3}, {%4,%5,%6,%7}, {%8,%9}, {%0,%1,%2,%3};"
        : "+f"(d[0]), "+f"(d[1]), "+f"(d[2]), "+f"(d[3])
        : "r"(a[0]), "r"(a[1]), "r"(a[2]), "r"(a[3]), "r"(b[0]), "r"(b[1]));
}

// ---------------------------------------------------------------------------
// hi/lo bf16 split helpers
// ---------------------------------------------------------------------------
__device__ __forceinline__ void split_pack2(float x0, float x1, uint32_t& hp, uint32_t& lp) {
    __nv_bfloat16 h0 = __float2bfloat16_rn(x0);
    __nv_bfloat16 h1 = __float2bfloat16_rn(x1);
    __nv_bfloat16 l0 = __float2bfloat16_rn(x0 - __bfloat162float(h0));
    __nv_bfloat16 l1 = __float2bfloat16_rn(x1 - __bfloat162float(h1));
    hp = (uint32_t)__bfloat16_as_ushort(h0) | ((uint32_t)__bfloat16_as_ushort(h1) << 16);
    lp = (uint32_t)__bfloat16_as_ushort(l0) | ((uint32_t)__bfloat16_as_ushort(l1) << 16);
}

// Elementwise fp32 -> (hi, lo) bf16. slot 0..2 -> A slots (src arg);
// slot 3 -> W slot 3 (Wo, src arg); slot 4 -> C (src = g_ctx, arg ignored).
__global__ __launch_bounds__(256)
void cvt_split_kernel(const float* __restrict__ src, int slot, int n4)
{
    int i = blockIdx.x * 256 + threadIdx.x;
    if (i >= n4) return;
    __nv_bfloat16 *hi, *lo;
    const float* s = src;
    if (slot < 3)       { hi = g_Ahi + (size_t)slot * M_TOTAL * D_MODEL;
                          lo = g_Alo + (size_t)slot * M_TOTAL * D_MODEL; }
    else if (slot == 3) { hi = g_Whi + 3ull * D_MODEL * D_MODEL;
                          lo = g_Wlo + 3ull * D_MODEL * D_MODEL; }
    else                { hi = g_Chi; lo = g_Clo; s = g_ctx; }
    float4 v = ((const float4*)s)[i];
    uint32_t h01, l01, h23, l23;
    split_pack2(v.x, v.y, h01, l01);
    split_pack2(v.z, v.w, h23, l23);
    ((uint2*)hi)[i] = make_uint2(h01, h23);
    ((uint2*)lo)[i] = make_uint2(l01, l23);
}

// Transpose-convert head-blocked W[h, d, dk] -> K-major [n=h*64+dk][k=d] hi/lo bf16.
__global__ __launch_bounds__(256)
void prep_w_kernel(const float* __restrict__ Wq, const float* __restrict__ Wk,
                   const float* __restrict__ Wv)
{
    const int z = blockIdx.z;
    const float* W = (z == 0) ? Wq : ((z == 1) ? Wk : Wv);
    __nv_bfloat16* hi = g_Whi + (size_t)z * D_MODEL * D_MODEL;
    __nv_bfloat16* lo = g_Wlo + (size_t)z * D_MODEL * D_MODEL;
    const int h  = blockIdx.y;
    const int d0 = blockIdx.x * 64;
    __shared__ float s[64][65];
    const int tid = threadIdx.x;
#pragma unroll
    for (int i = 0; i < 4; i++) {
        int f = tid + i * 256;
        int d = f >> 4;
        int c = (f & 15) * 4;
        float4 v = *(const float4*)(W + (size_t)h * (D_MODEL * DK) + (size_t)(d0 + d) * DK + c);
        s[d][c + 0] = v.x; s[d][c + 1] = v.y; s[d][c + 2] = v.z; s[d][c + 3] = v.w;
    }
    __syncthreads();
#pragma unroll
    for (int i = 0; i < 4; i++) {
        int f  = tid + i * 256;
        int dk = f >> 4;
        int dd = (f & 15) * 4;
        float x0 = s[dd + 0][dk], x1 = s[dd + 1][dk], x2 = s[dd + 2][dk], x3 = s[dd + 3][dk];
        uint32_t h01, l01, h23, l23;
        split_pack2(x0, x1, h01, l01);
        split_pack2(x2, x3, h23, l23);
        size_t o = ((size_t)(h * 64 + dk)) * D_MODEL + d0 + dd;
        *(uint2*)(hi + o) = make_uint2(h01, h23);
        *(uint2*)(lo + o) = make_uint2(l01, l23);
    }
}

// ---------------------------------------------------------------------------
// HMMA GEMM: C[128x128 tile] = A(4096x1024) x B(1024x1024)^T (+bias)
// bf16 split: D = Ah*Bh + Ah*Bl + Al*Bh, fp32 accumulate in registers.
// Block 256 thr = 8 warps (2m x 4n), warp tile 64x32, mma.m16n8k16.
// SMEM stage (double buffered): Ah/Al/Bh/Bl each 128 rows x 32 bf16,
// row stride 40 bf16 (80 B) -> conflict-free ldmatrix phases.
// ---------------------------------------------------------------------------
#define GST_A_H 0
#define GST_A_L 10240
#define GST_B_H 20480
#define GST_B_L 30720
#define GSTAGE  40960
#define GSMEM_TOTAL (2 * GSTAGE)   // 81920 B

template <bool IS_PROJ>
__global__ __launch_bounds__(256)
void gemm_mma(const float* __restrict__ bq, const float* __restrict__ bk,
              const float* __restrict__ bv, const float* __restrict__ bo,
              float* __restrict__ OutG)
{
    extern __shared__ char gsm[];
    const uint32_t sb = smem_to_u32(gsm);
    const int tid    = threadIdx.x;
    const int wid    = tid >> 5;
    const int lane   = tid & 31;
    const int warp_m = wid >> 2;      // 0..1
    const int warp_n = wid & 3;       // 0..3

    const __nv_bfloat16 *gAh, *gAl, *gBh, *gBl;
    const float* bias;
    float* Cptr;
    if (IS_PROJ) {
        const int z = blockIdx.z;
        gAh = g_Ahi + (size_t)z * M_TOTAL * D_MODEL;
        gAl = g_Alo + (size_t)z * M_TOTAL * D_MODEL;
        gBh = g_Whi + (size_t)z * D_MODEL * D_MODEL;
        gBl = g_Wlo + (size_t)z * D_MODEL * D_MODEL;
        bias = (z == 0) ? bq : ((z == 1) ? bk : bv);
        Cptr = (z == 0) ? g_Qh : ((z == 1) ? g_Kh : g_Vh);
    } else {
        gAh = g_Chi;  gAl = g_Clo;
        gBh = g_Whi + (size_t)3 * D_MODEL * D_MODEL;
        gBl = g_Wlo + (size_t)3 * D_MODEL * D_MODEL;
        bias = bo;  Cptr = OutG;
    }
    const int m0 = blockIdx.y * 128;
    const int n0 = blockIdx.x * 128;

    // per-thread load mapping: 2 chunks of 8 bf16 per array per stage
    const int ld_row0 = (tid * 2) >> 2;          // idx = tid*2 + i, row = idx>>2
    const int ld_c0   = ((tid * 2) & 3);         // 0..3 (16B units)

    float acc[4][4][4];
#pragma unroll
    for (int mf = 0; mf < 4; mf++)
#pragma unroll
        for (int nf = 0; nf < 4; nf++)
#pragma unroll
            for (int e = 0; e < 4; e++) acc[mf][nf][e] = 0.0f;

    // ldmatrix base addresses (per thread)
    const uint32_t aOff = (uint32_t)((warp_m * 64 + (lane & 15)) * 80 + ((lane >> 4) * 16));
    const uint32_t bOff = (uint32_t)((warp_n * 32 + ((lane >> 4) << 3) + (lane & 7)) * 80
                                     + (((lane >> 3) & 1) * 16));

    auto issue_stage = [&](int ch, int buf) {
        const int k0 = ch * 32;
        const uint32_t stg = sb + buf * GSTAGE;
#pragma unroll
        for (int i = 0; i < 2; i++) {
            const int row = ld_row0 + ((ld_c0 + i) >> 2);        // idx>>2
            const int c   = (ld_c0 + i) & 3;                     // 16B unit in row
            const uint32_t so = (uint32_t)(row * 80 + c * 16);
            const size_t gaoff = (size_t)(m0 + row) * D_MODEL + k0 + c * 8;
            const size_t gboff = (size_t)(n0 + row) * D_MODEL + k0 + c * 8;
            CP_ASYNC16(stg + GST_A_H + so, gAh + gaoff);
            CP_ASYNC16(stg + GST_A_L + so, gAl + gaoff);
            CP_ASYNC16(stg + GST_B_H + so, gBh + gboff);
            CP_ASYNC16(stg + GST_B_L + so, gBl + gboff);
        }
    };

    issue_stage(0, 0);
    CP_COMMIT();

    for (int ch = 0; ch < 32; ++ch) {
        const int buf = ch & 1;
        if (ch + 1 < 32) {
            issue_stage(ch + 1, buf ^ 1);
            CP_COMMIT();
            CP_WAIT1();
        } else {
            CP_WAIT0();
        }
        __syncthreads();

        const uint32_t stg = sb + buf * GSTAGE;
#pragma unroll
        for (int k16 = 0; k16 < 2; ++k16) {
            const uint32_t kb = k16 * 32;
            uint32_t ah[4][4], al[4][4];
#pragma unroll
            for (int mf = 0; mf < 4; mf++) {
                const uint32_t ao = stg + aOff + mf * (16 * 80) + kb;
                ldsm_x4(ah[mf][0], ah[mf][1], ah[mf][2], ah[mf][3], ao + GST_A_H);
                ldsm_x4(al[mf][0], al[mf][1], al[mf][2], al[mf][3], ao + GST_A_L);
            }
            uint32_t bh[4][2], bl[4][2];
#pragma unroll
            for (int nf2 = 0; nf2 < 2; nf2++) {
                const uint32_t bo_ = stg + bOff + nf2 * (16 * 80) + kb;
                ldsm_x4(bh[nf2 * 2][0], bh[nf2 * 2][1], bh[nf2 * 2 + 1][0], bh[nf2 * 2 + 1][1],
                        bo_ + GST_B_H);
                ldsm_x4(bl[nf2 * 2][0], bl[nf2 * 2][1], bl[nf2 * 2 + 1][0], bl[nf2 * 2 + 1][1],
                        bo_ + GST_B_L);
            }
#pragma unroll
            for (int mf = 0; mf < 4; mf++) {
#pragma unroll
                for (int nf = 0; nf < 4; nf++) {
                    mma_16816(acc[mf][nf], ah[mf], bh[nf]);   // Ah*Bh
                    mma_16816(acc[mf][nf], ah[mf], bl[nf]);   // Ah*Bl
                    mma_16816(acc[mf][nf], al[mf], bh[nf]);   // Al*Bh
                }
            }
        }
        __syncthreads();   // protect buf from next iteration's cp.async overwrite
    }

    // Epilogue: fragment layout c0,c1 = (row lane/4, col 2*(lane%4)+{0,1}); c2,c3 = row+8.
    const int lr = lane >> 2;
    const int lc = (lane & 3) * 2;
#pragma unroll
    for (int mf = 0; mf < 4; ++mf) {
        const int mA = m0 + warp_m * 64 + mf * 16 + lr;
#pragma unroll
        for (int nf = 0; nf < 4; ++nf) {
            const int col = n0 + warp_n * 32 + nf * 8 + lc;
            const float b0v = bias[col];
            const float b1v = bias[col + 1];
            float *p0, *p1;
            if (IS_PROJ) {
                const int h  = col >> 6;
                const int kk = col & 63;
                const int b0i = mA >> 11, t0 = mA & (SEQ - 1);
                const int b1i = (mA + 8) >> 11, t1 = (mA + 8) & (SEQ - 1);
                p0 = Cptr + (((size_t)(b0i * NHEADS + h)) * SEQ + t0) * DK + kk;
                p1 = Cptr + (((size_t)(b1i * NHEADS + h)) * SEQ + t1) * DK + kk;
            } else {
                p0 = Cptr + (size_t)mA * D_MODEL + col;
                p1 = Cptr + (size_t)(mA + 8) * D_MODEL + col;
            }
            *(float2*)p0 = make_float2(acc[mf][nf][0] + b0v, acc[mf][nf][1] + b1v);
            *(float2*)p1 = make_float2(acc[mf][nf][2] + b0v, acc[mf][nf][3] + b1v);
        }
    }
}

// ---------------------------------------------------------------------------
// Flash attention per (b,h) — unchanged from the passing R9 kernel.
// ---------------------------------------------------------------------------
__global__ __launch_bounds__(256, 2)
void attn_kernel()
{
    extern __shared__ float sm[];
    float* Qs = sm;                       // [128][65]
    float* Ks = Qs + 128 * 65;            // [64][65]
    float* Vs = Ks + 64 * 65;             // [64][64]
    float* Ps = Vs + 64 * 64;             // [128][65]

    const int bh = blockIdx.y;
    const int q0 = blockIdx.x * 128;
    const float* Qbase = g_Qh + (size_t)bh * SEQ * DK;
    const float* Kbase = g_Kh + (size_t)bh * SEQ * DK;
    const float* Vbase = g_Vh + (size_t)bh * SEQ * DK;
    float*       Cbase = g_ctx + (size_t)bh * SEQ * DK;

    const int tid = threadIdx.x;
    const int tx  = tid & 15;
    const int ty  = tid >> 4;
    const float scale = 0.125f;

#pragma unroll
    for (int i = 0; i < 8; i++) {
        const int idx = tid + i * 256;
        const int r   = idx >> 4;
        const int c   = (idx & 15) * 4;
        float4 v = *(const float4*)(Qbase + (size_t)(q0 + r) * DK + c);
        Qs[r * 65 + c + 0] = v.x;
        Qs[r * 65 + c + 1] = v.y;
        Qs[r * 65 + c + 2] = v.z;
        Qs[r * 65 + c + 3] = v.w;
    }

    float m_i[8], l_i[8], O[8][4];
#pragma unroll
    for (int i = 0; i < 8; i++) {
        m_i[i] = -1e30f;
        l_i[i] = 0.0f;
#pragma unroll
        for (int j = 0; j < 4; j++) O[i][j] = 0.0f;
    }

    for (int s0 = 0; s0 < SEQ; s0 += 64) {
        __syncthreads();
#pragma unroll
        for (int i = 0; i < 4; i++) {
            const int idx = tid + i * 256;
            const int r   = idx >> 4;
            const int c   = (idx & 15) * 4;
            float4 kv = *(const float4*)(Kbase + (size_t)(s0 + r) * DK + c);
            Ks[r * 65 + c + 0] = kv.x;
            Ks[r * 65 + c + 1] = kv.y;
            Ks[r * 65 + c + 2] = kv.z;
            Ks[r * 65 + c + 3] = kv.w;
            float4 vv = *(const float4*)(Vbase + (size_t)(s0 + r) * DK + c);
            *(float4*)(Vs + r * 64 + c) = vv;
        }
        __syncthreads();

        float s_acc[8][4];
#pragma unroll
        for (int i = 0; i < 8; i++)
#pragma unroll
            for (int j = 0; j < 4; j++) s_acc[i][j] = 0.0f;

#pragma unroll 4
        for (int kk = 0; kk < 64; kk++) {
            float a[8], bv[4];
#pragma unroll
            for (int i = 0; i < 8; i++) a[i] = Qs[(ty * 8 + i) * 65 + kk];
#pragma unroll
            for (int j = 0; j < 4; j++) bv[j] = Ks[(tx * 4 + j) * 65 + kk];
#pragma unroll
            for (int i = 0; i < 8; i++)
#pragma unroll
                for (int j = 0; j < 4; j++)
                    s_acc[i][j] = fmaf(a[i], bv[j], s_acc[i][j]);
        }

#pragma unroll
        for (int i = 0; i < 8; i++) {
            float mt = -1e30f;
#pragma unroll
            for (int j = 0; j < 4; j++) {
                s_acc[i][j] *= scale;
                mt = fmaxf(mt, s_acc[i][j]);
            }
#pragma unroll
            for (int off = 8; off >= 1; off >>= 1)
                mt = fmaxf(mt, __shfl_xor_sync(0xffffffffu, mt, off));

            const float m_new = fmaxf(m_i[i], mt);
            const float alpha = __expf(m_i[i] - m_new);
            float rs = 0.0f;
#pragma unroll
            for (int j = 0; j < 4; j++) {
                const float p = __expf(s_acc[i][j] - m_new);
                s_acc[i][j] = p;
                rs += p;
            }
#pragma unroll
            for (int off = 8; off >= 1; off >>= 1)
                rs += __shfl_xor_sync(0xffffffffu, rs, off);

            l_i[i] = l_i[i] * alpha + rs;
            m_i[i] = m_new;
#pragma unroll
            for (int j = 0; j < 4; j++) O[i][j] *= alpha;
#pragma unroll
            for (int j = 0; j < 4; j++)
                Ps[(ty * 8 + i) * 65 + tx * 4 + j] = s_acc[i][j];
        }
        __syncthreads();

#pragma unroll 4
        for (int s = 0; s < 64; s++) {
            float a[8];
#pragma unroll
            for (int i = 0; i < 8; i++) a[i] = Ps[(ty * 8 + i) * 65 + s];
            const float4 vv = *(const float4*)(Vs + s * 64 + tx * 4);
#pragma unroll
            for (int i = 0; i < 8; i++) {
                O[i][0] = fmaf(a[i], vv.x, O[i][0]);
                O[i][1] = fmaf(a[i], vv.y, O[i][1]);
                O[i][2] = fmaf(a[i], vv.z, O[i][2]);
                O[i][3] = fmaf(a[i], vv.w, O[i][3]);
            }
        }
    }

#pragma unroll
    for (int i = 0; i < 8; i++) {
        const float inv = 1.0f / l_i[i];
        const int r = q0 + ty * 8 + i;
#pragma unroll
        for (int j = 0; j < 4; j++)
            Cbase[(size_t)r * DK + tx * 4 + j] = O[i][j] * inv;
    }
}

// ---------------------------------------------------------------------------
extern "C" void kernel_launch(void* const* d_in, const int* in_sizes, int n_in,
                              void* d_out, int out_size)
{
    (void)in_sizes; (void)n_in; (void)out_size;
    const float* Q  = (const float*)d_in[0];
    const float* K  = (const float*)d_in[1];
    const float* V  = (const float*)d_in[2];
    const float* Wq = (const float*)d_in[3];
    const float* bq = (const float*)d_in[4];
    const float* Wk = (const float*)d_in[5];
    const float* bk = (const float*)d_in[6];
    const float* Wv = (const float*)d_in[7];
    const float* bv = (const float*)d_in[8];
    const float* Wo = (const float*)d_in[9];
    const float* bo = (const float*)d_in[10];
    float* Out = (float*)d_out;

    cudaFuncSetAttribute((const void*)gemm_mma<true>,
                         cudaFuncAttributeMaxDynamicSharedMemorySize, GSMEM_TOTAL);
    cudaFuncSetAttribute((const void*)gemm_mma<false>,
                         cudaFuncAttributeMaxDynamicSharedMemorySize, GSMEM_TOTAL);

    const int nA4 = (M_TOTAL * D_MODEL) / 4;         // 1,048,576
    const int nW4 = (D_MODEL * D_MODEL) / 4;         // 262,144

    // 1) split-convert inputs + weights
    cvt_split_kernel<<<nA4 / 256, 256>>>(Q, 0, nA4);
    cvt_split_kernel<<<nA4 / 256, 256>>>(K, 1, nA4);
    cvt_split_kernel<<<nA4 / 256, 256>>>(V, 2, nA4);
    cvt_split_kernel<<<nW4 / 256, 256>>>(Wo, 3, nW4);
    prep_w_kernel<<<dim3(D_MODEL / 64, NHEADS, 3), 256>>>(Wq, Wk, Wv);

    // 2) QKV projections on HMMA tensor cores: grid (N/128, M/128, 3)
    gemm_mma<true><<<dim3(D_MODEL / 128, M_TOTAL / 128, 3), 256, GSMEM_TOTAL>>>(
        bq, bk, bv, bo, Out);

    // 3) flash attention (fp32, unchanged)
    const int ATTN_SMEM = (128 * 65 + 64 * 65 + 64 * 64 + 128 * 65) * (int)sizeof(float);
    cudaFuncSetAttribute((const void*)attn_kernel,
                         cudaFuncAttributeMaxDynamicSharedMemorySize, ATTN_SMEM);
    attn_kernel<<<dim3(SEQ / 128, BATCH * NHEADS), 256, ATTN_SMEM>>>();

    // 4) split-convert ctx, then output projection on HMMA tensor cores
    cvt_split_kernel<<<nA4 / 256, 256>>>(Q /*ignored*/, 4, nA4);
    gemm_mma<false><<<dim3(D_MODEL / 128, M_TOTAL / 128, 1), 256, GSMEM_TOTAL>>>(
        bq, bk, bv, bo, Out);
}

// round 16
// speedup vs baseline: 2.3717x; 1.8102x over previous
#include <cuda_runtime.h>
#include <cuda_bf16.h>
#include <math.h>
#include <stdint.h>

#define D_MODEL 1024
#define NHEADS  16
#define DK      64
#define BATCH   2
#define SEQ     2048
#define M_TOTAL (BATCH * SEQ)                    // 4096
#define HEAD_ELEMS (BATCH * NHEADS * SEQ * DK)   // 4,194,304

// ---------------- scratch (__device__ globals; allocation guards forbid cudaMalloc)
// GEMM inputs (hi/lo bf16 split)
__device__ __nv_bfloat16 g_Ahi[3ull * M_TOTAL * D_MODEL];
__device__ __nv_bfloat16 g_Alo[3ull * M_TOTAL * D_MODEL];
__device__ __nv_bfloat16 g_Whi[4ull * D_MODEL * D_MODEL];  // [Wq,Wk,Wv,Wo] K-major [n][k]
__device__ __nv_bfloat16 g_Wlo[4ull * D_MODEL * D_MODEL];
// Projected heads, hi/lo bf16, layout [b,h,t,dk]. Q is pre-scaled by 1/8.
__device__ __nv_bfloat16 g_Qbh[HEAD_ELEMS], g_Qbl[HEAD_ELEMS];
__device__ __nv_bfloat16 g_Kbh[HEAD_ELEMS], g_Kbl[HEAD_ELEMS];
__device__ __nv_bfloat16 g_Vbh[HEAD_ELEMS], g_Vbl[HEAD_ELEMS];
// ctx hi/lo (A operand of the output projection, read as flat [4096][1024])
__device__ __nv_bfloat16 g_Chi[(size_t)M_TOTAL * D_MODEL];
__device__ __nv_bfloat16 g_Clo[(size_t)M_TOTAL * D_MODEL];

// ---------------- PTX helpers (sm_80-era: valid under compute_103 virtual target)
__device__ __forceinline__ uint32_t smem_to_u32(const void* p) {
    uint32_t a;
    asm("{ .reg .u64 t; cvta.to.shared.u64 t, %1; cvt.u32.u64 %0, t; }" : "=r"(a) : "l"(p));
    return a;
}
#define CP_ASYNC16(smem_addr, gptr) \
    asm volatile("cp.async.cg.shared.global [%0], [%1], 16;" :: "r"((uint32_t)(smem_addr)), "l"(gptr))
#define CP_COMMIT() asm volatile("cp.async.commit_group;" ::: "memory")
#define CP_WAIT1()  asm volatile("cp.async.wait_group 1;" ::: "memory")
#define CP_WAIT0()  asm volatile("cp.async.wait_group 0;" ::: "memory")

__device__ __forceinline__ void ldsm_x4(uint32_t& r0, uint32_t& r1, uint32_t& r2, uint32_t& r3,
                                        uint32_t addr) {
    asm volatile("ldmatrix.sync.aligned.m8n8.x4.shared.b16 {%0,%1,%2,%3}, [%4];"
                 : "=r"(r0), "=r"(r1), "=r"(r2), "=r"(r3) : "r"(addr));
}
__device__ __forceinline__ void ldsm_x4_t(uint32_t& r0, uint32_t& r1, uint32_t& r2, uint32_t& r3,
                                          uint32_t addr) {
    asm volatile("ldmatrix.sync.aligned.m8n8.x4.trans.shared.b16 {%0,%1,%2,%3}, [%4];"
                 : "=r"(r0), "=r"(r1), "=r"(r2), "=r"(r3) : "r"(addr));
}
__device__ __forceinline__ void mma_16816(float* d, const uint32_t* a, const uint32_t* b) {
    asm volatile(
        "mma.sync.aligned.m16n8k16.row.col.f32.bf16.bf16.f32 "
        "{%0,%1,%2,%3}, {%4,%5,%6,%7}, {%8,%9}, {%0,%1,%2,%3};"
        : "+f"(d[0]), "+f"(d[1]), "+f"(d[2]), "+f"(d[3])
        : "r"(a[0]), "r"(a[1]), "r"(a[2]), "r"(a[3]), "r"(b[0]), "r"(b[1]));
}

// ---------------------------------------------------------------------------
// hi/lo bf16 split helpers
// ---------------------------------------------------------------------------
__device__ __forceinline__ void split_pack2(float x0, float x1, uint32_t& hp, uint32_t& lp) {
    __nv_bfloat16 h0 = __float2bfloat16_rn(x0);
    __nv_bfloat16 h1 = __float2bfloat16_rn(x1);
    __nv_bfloat16 l0 = __float2bfloat16_rn(x0 - __bfloat162float(h0));
    __nv_bfloat16 l1 = __float2bfloat16_rn(x1 - __bfloat162float(h1));
    hp = (uint32_t)__bfloat16_as_ushort(h0) | ((uint32_t)__bfloat16_as_ushort(h1) << 16);
    lp = (uint32_t)__bfloat16_as_ushort(l0) | ((uint32_t)__bfloat16_as_ushort(l1) << 16);
}

// Elementwise fp32 -> (hi, lo) bf16. slot 0..2 -> A slots; slot 3 -> W slot 3 (Wo).
__global__ __launch_bounds__(256)
void cvt_split_kernel(const float* __restrict__ src, int slot, int n4)
{
    int i = blockIdx.x * 256 + threadIdx.x;
    if (i >= n4) return;
    __nv_bfloat16 *hi, *lo;
    if (slot < 3) { hi = g_Ahi + (size_t)slot * M_TOTAL * D_MODEL;
                    lo = g_Alo + (size_t)slot * M_TOTAL * D_MODEL; }
    else          { hi = g_Whi + 3ull * D_MODEL * D_MODEL;
                    lo = g_Wlo + 3ull * D_MODEL * D_MODEL; }
    float4 v = ((const float4*)src)[i];
    uint32_t h01, l01, h23, l23;
    split_pack2(v.x, v.y, h01, l01);
    split_pack2(v.z, v.w, h23, l23);
    ((uint2*)hi)[i] = make_uint2(h01, h23);
    ((uint2*)lo)[i] = make_uint2(l01, l23);
}

// Transpose-convert head-blocked W[h, d, dk] -> K-major [n=h*64+dk][k=d] hi/lo bf16.
__global__ __launch_bounds__(256)
void prep_w_kernel(const float* __restrict__ Wq, const float* __restrict__ Wk,
                   const float* __restrict__ Wv)
{
    const int z = blockIdx.z;
    const float* W = (z == 0) ? Wq : ((z == 1) ? Wk : Wv);
    __nv_bfloat16* hi = g_Whi + (size_t)z * D_MODEL * D_MODEL;
    __nv_bfloat16* lo = g_Wlo + (size_t)z * D_MODEL * D_MODEL;
    const int h  = blockIdx.y;
    const int d0 = blockIdx.x * 64;
    __shared__ float s[64][65];
    const int tid = threadIdx.x;
#pragma unroll
    for (int i = 0; i < 4; i++) {
        int f = tid + i * 256;
        int d = f >> 4;
        int c = (f & 15) * 4;
        float4 v = *(const float4*)(W + (size_t)h * (D_MODEL * DK) + (size_t)(d0 + d) * DK + c);
        s[d][c + 0] = v.x; s[d][c + 1] = v.y; s[d][c + 2] = v.z; s[d][c + 3] = v.w;
    }
    __syncthreads();
#pragma unroll
    for (int i = 0; i < 4; i++) {
        int f  = tid + i * 256;
        int dk = f >> 4;
        int dd = (f & 15) * 4;
        float x0 = s[dd + 0][dk], x1 = s[dd + 1][dk], x2 = s[dd + 2][dk], x3 = s[dd + 3][dk];
        uint32_t h01, l01, h23, l23;
        split_pack2(x0, x1, h01, l01);
        split_pack2(x2, x3, h23, l23);
        size_t o = ((size_t)(h * 64 + dk)) * D_MODEL + d0 + dd;
        *(uint2*)(hi + o) = make_uint2(h01, h23);
        *(uint2*)(lo + o) = make_uint2(l01, l23);
    }
}

// ---------------------------------------------------------------------------
// HMMA GEMM (as R15): C = A x B^T (+bias). bf16 split: Ah*Bh + Ah*Bl + Al*Bh.
// IS_PROJ epilogue writes hi/lo bf16 into [B,H,T,DK] (Q pre-scaled by 1/8).
// ---------------------------------------------------------------------------
#define GST_A_H 0
#define GST_A_L 10240
#define GST_B_H 20480
#define GST_B_L 30720
#define GSTAGE  40960
#define GSMEM_TOTAL (2 * GSTAGE)   // 81920 B

template <bool IS_PROJ>
__global__ __launch_bounds__(256)
void gemm_mma(const float* __restrict__ bq, const float* __restrict__ bk,
              const float* __restrict__ bv, const float* __restrict__ bo,
              float* __restrict__ OutG)
{
    extern __shared__ char gsm[];
    const uint32_t sb = smem_to_u32(gsm);
    const int tid    = threadIdx.x;
    const int wid    = tid >> 5;
    const int lane   = tid & 31;
    const int warp_m = wid >> 2;
    const int warp_n = wid & 3;

    const __nv_bfloat16 *gAh, *gAl, *gBh, *gBl;
    const float* bias;
    if (IS_PROJ) {
        const int z = blockIdx.z;
        gAh = g_Ahi + (size_t)z * M_TOTAL * D_MODEL;
        gAl = g_Alo + (size_t)z * M_TOTAL * D_MODEL;
        gBh = g_Whi + (size_t)z * D_MODEL * D_MODEL;
        gBl = g_Wlo + (size_t)z * D_MODEL * D_MODEL;
        bias = (blockIdx.z == 0) ? bq : ((blockIdx.z == 1) ? bk : bv);
    } else {
        gAh = g_Chi;  gAl = g_Clo;
        gBh = g_Whi + (size_t)3 * D_MODEL * D_MODEL;
        gBl = g_Wlo + (size_t)3 * D_MODEL * D_MODEL;
        bias = bo;
    }
    const int m0 = blockIdx.y * 128;
    const int n0 = blockIdx.x * 128;

    const int ld_row0 = (tid * 2) >> 2;
    const int ld_c0   = ((tid * 2) & 3);

    float acc[4][4][4];
#pragma unroll
    for (int mf = 0; mf < 4; mf++)
#pragma unroll
        for (int nf = 0; nf < 4; nf++)
#pragma unroll
            for (int e = 0; e < 4; e++) acc[mf][nf][e] = 0.0f;

    const uint32_t aOff = (uint32_t)((warp_m * 64 + (lane & 15)) * 80 + ((lane >> 4) * 16));
    const uint32_t bOff = (uint32_t)((warp_n * 32 + ((lane >> 4) << 3) + (lane & 7)) * 80
                                     + (((lane >> 3) & 1) * 16));

    auto issue_stage = [&](int ch, int buf) {
        const int k0 = ch * 32;
        const uint32_t stg = sb + buf * GSTAGE;
#pragma unroll
        for (int i = 0; i < 2; i++) {
            const int row = ld_row0 + ((ld_c0 + i) >> 2);
            const int c   = (ld_c0 + i) & 3;
            const uint32_t so = (uint32_t)(row * 80 + c * 16);
            const size_t gaoff = (size_t)(m0 + row) * D_MODEL + k0 + c * 8;
            const size_t gboff = (size_t)(n0 + row) * D_MODEL + k0 + c * 8;
            CP_ASYNC16(stg + GST_A_H + so, gAh + gaoff);
            CP_ASYNC16(stg + GST_A_L + so, gAl + gaoff);
            CP_ASYNC16(stg + GST_B_H + so, gBh + gboff);
            CP_ASYNC16(stg + GST_B_L + so, gBl + gboff);
        }
    };

    issue_stage(0, 0);
    CP_COMMIT();

    for (int ch = 0; ch < 32; ++ch) {
        const int buf = ch & 1;
        if (ch + 1 < 32) {
            issue_stage(ch + 1, buf ^ 1);
            CP_COMMIT();
            CP_WAIT1();
        } else {
            CP_WAIT0();
        }
        __syncthreads();

        const uint32_t stg = sb + buf * GSTAGE;
#pragma unroll
        for (int k16 = 0; k16 < 2; ++k16) {
            const uint32_t kb = k16 * 32;
            uint32_t ah[4][4], al[4][4];
#pragma unroll
            for (int mf = 0; mf < 4; mf++) {
                const uint32_t ao = stg + aOff + mf * (16 * 80) + kb;
                ldsm_x4(ah[mf][0], ah[mf][1], ah[mf][2], ah[mf][3], ao + GST_A_H);
                ldsm_x4(al[mf][0], al[mf][1], al[mf][2], al[mf][3], ao + GST_A_L);
            }
            uint32_t bh[4][2], bl[4][2];
#pragma unroll
            for (int nf2 = 0; nf2 < 2; nf2++) {
                const uint32_t bo_ = stg + bOff + nf2 * (16 * 80) + kb;
                ldsm_x4(bh[nf2 * 2][0], bh[nf2 * 2][1], bh[nf2 * 2 + 1][0], bh[nf2 * 2 + 1][1],
                        bo_ + GST_B_H);
                ldsm_x4(bl[nf2 * 2][0], bl[nf2 * 2][1], bl[nf2 * 2 + 1][0], bl[nf2 * 2 + 1][1],
                        bo_ + GST_B_L);
            }
#pragma unroll
            for (int mf = 0; mf < 4; mf++) {
#pragma unroll
                for (int nf = 0; nf < 4; nf++) {
                    mma_16816(acc[mf][nf], ah[mf], bh[nf]);
                    mma_16816(acc[mf][nf], ah[mf], bl[nf]);
                    mma_16816(acc[mf][nf], al[mf], bh[nf]);
                }
            }
        }
        __syncthreads();
    }

    const int lr = lane >> 2;
    const int lc = (lane & 3) * 2;
    if (IS_PROJ) {
        __nv_bfloat16 *Ohi, *Olo;
        float scl;
        if (blockIdx.z == 0)      { Ohi = g_Qbh; Olo = g_Qbl; scl = 0.125f; }
        else if (blockIdx.z == 1) { Ohi = g_Kbh; Olo = g_Kbl; scl = 1.0f; }
        else                      { Ohi = g_Vbh; Olo = g_Vbl; scl = 1.0f; }
#pragma unroll
        for (int mf = 0; mf < 4; ++mf) {
            const int mA = m0 + warp_m * 64 + mf * 16 + lr;
#pragma unroll
            for (int nf = 0; nf < 4; ++nf) {
                const int col = n0 + warp_n * 32 + nf * 8 + lc;
                const float b0v = bias[col], b1v = bias[col + 1];
                const int h  = col >> 6;
                const int kk = col & 63;
                const int b0i = mA >> 11, t0 = mA & (SEQ - 1);
                const int b1i = (mA + 8) >> 11, t1 = (mA + 8) & (SEQ - 1);
                const size_t o0 = (((size_t)(b0i * NHEADS + h)) * SEQ + t0) * DK + kk;
                const size_t o1 = (((size_t)(b1i * NHEADS + h)) * SEQ + t1) * DK + kk;
                uint32_t hp, lp;
                split_pack2((acc[mf][nf][0] + b0v) * scl, (acc[mf][nf][1] + b1v) * scl, hp, lp);
                *(uint32_t*)(Ohi + o0) = hp;  *(uint32_t*)(Olo + o0) = lp;
                split_pack2((acc[mf][nf][2] + b0v) * scl, (acc[mf][nf][3] + b1v) * scl, hp, lp);
                *(uint32_t*)(Ohi + o1) = hp;  *(uint32_t*)(Olo + o1) = lp;
            }
        }
    } else {
#pragma unroll
        for (int mf = 0; mf < 4; ++mf) {
            const int mA = m0 + warp_m * 64 + mf * 16 + lr;
#pragma unroll
            for (int nf = 0; nf < 4; ++nf) {
                const int col = n0 + warp_n * 32 + nf * 8 + lc;
                const float b0v = bias[col], b1v = bias[col + 1];
                float* p0 = OutG + (size_t)mA * D_MODEL + col;
                float* p1 = OutG + (size_t)(mA + 8) * D_MODEL + col;
                *(float2*)p0 = make_float2(acc[mf][nf][0] + b0v, acc[mf][nf][1] + b1v);
                *(float2*)p1 = make_float2(acc[mf][nf][2] + b0v, acc[mf][nf][3] + b1v);
            }
        }
    }
}

// ---------------------------------------------------------------------------
// HMMA flash attention. Per (b,h); 128 q-rows/CTA, 8 warps x 16 rows.
// Key loop in tiles of 64, double-buffered cp.async (Kh,Kl,Vh,Vl).
// QK^T: Qh*Kh + Ql*Kh + Qh*Kl  (Q pre-scaled by 1/8 at projection).
// P split in regs: Ph*Vh + Pl*Vh + Ph*Vl; V B-frags via ldmatrix.trans.
// Epilogue writes ctx hi/lo bf16 directly for the output GEMM.
// ---------------------------------------------------------------------------
#define ATT_RB   144                 // bytes per smem row (72 bf16: conflict-free ldsm)
#define A_QH     0
#define A_QL     (128 * ATT_RB)      // 18432
#define A_STG    (2 * 128 * ATT_RB)  // 36864
#define A_STGSZ  (4 * 64 * ATT_RB)   // 36864: Kh | Kl | Vh | Vl
#define A_KH     0
#define A_KL     (64 * ATT_RB)
#define A_VH     (2 * 64 * ATT_RB)
#define A_VL     (3 * 64 * ATT_RB)
#define ATT_SMEM (A_STG + 2 * A_STGSZ)   // 110592

__global__ __launch_bounds__(256)
void attn_mma()
{
    extern __shared__ char smem[];
    const uint32_t sb = smem_to_u32(smem);
    const int tid  = threadIdx.x;
    const int wid  = tid >> 5;
    const int lane = tid & 31;
    const int gid  = lane >> 2;      // row within frag
    const int tig  = lane & 3;       // col pair

    const int bh = blockIdx.y;
    const int q0 = blockIdx.x * 128;
    const __nv_bfloat16* gQh = g_Qbh + (size_t)bh * SEQ * DK;
    const __nv_bfloat16* gQl = g_Qbl + (size_t)bh * SEQ * DK;
    const __nv_bfloat16* gKh = g_Kbh + (size_t)bh * SEQ * DK;
    const __nv_bfloat16* gKl = g_Kbl + (size_t)bh * SEQ * DK;
    const __nv_bfloat16* gVh = g_Vbh + (size_t)bh * SEQ * DK;
    const __nv_bfloat16* gVl = g_Vbl + (size_t)bh * SEQ * DK;

    // ---- async loaders
    auto issue_q = [&] {
#pragma unroll
        for (int i = 0; i < 8; i++) {
            const int c   = tid + (i & 3) * 256;          // 0..1023
            const int row = c >> 3;
            const int off = c & 7;
            const uint32_t so = (uint32_t)(row * ATT_RB + off * 16);
            const size_t go = (size_t)(q0 + row) * DK + off * 8;
            if (i < 4) CP_ASYNC16(sb + A_QH + so, gQh + go);
            else       CP_ASYNC16(sb + A_QL + so, gQl + go);
        }
    };
    auto issue_stage = [&](int it, int buf) {
        const int s0 = it * 64;
        const uint32_t stg = sb + A_STG + buf * A_STGSZ;
#pragma unroll
        for (int i = 0; i < 8; i++) {
            const int arr = i >> 1;
            const int c   = tid + (i & 1) * 256;          // 0..511
            const int row = c >> 3;
            const int off = c & 7;
            const uint32_t so = (uint32_t)(arr * (64 * ATT_RB) + row * ATT_RB + off * 16);
            const size_t go = (size_t)(s0 + row) * DK + off * 8;
            const __nv_bfloat16* g = (arr == 0) ? gKh : ((arr == 1) ? gKl : ((arr == 2) ? gVh : gVl));
            CP_ASYNC16(stg + so, g + go);
        }
    };

    issue_q();
    issue_stage(0, 0);
    CP_COMMIT();

    float m_r[2] = {-1e30f, -1e30f};
    float l_r[2] = {0.0f, 0.0f};
    float octx[8][4];
#pragma unroll
    for (int n = 0; n < 8; n++)
#pragma unroll
        for (int e = 0; e < 4; e++) octx[n][e] = 0.0f;

    uint32_t qh[4][4], ql[4][4];

    const uint32_t qAddrBase = sb + (uint32_t)((16 * wid + (lane & 15)) * ATT_RB + (lane >> 4) * 16);
    const uint32_t kOff = (uint32_t)((((lane >> 4) << 3) + (lane & 7)) * ATT_RB + ((lane >> 3) & 1) * 16);
    const uint32_t vOff = (uint32_t)(((((lane >> 3) & 1) << 3) + (lane & 7)) * ATT_RB + (lane >> 4) * 16);

    for (int it = 0; it < SEQ / 64; ++it) {
        const int buf = it & 1;
        if (it + 1 < SEQ / 64) {
            issue_stage(it + 1, buf ^ 1);
            CP_COMMIT();
            CP_WAIT1();
        } else {
            CP_WAIT0();
        }
        __syncthreads();

        if (it == 0) {  // Q fragments: once, into registers
#pragma unroll
            for (int kf = 0; kf < 4; kf++) {
                ldsm_x4(qh[kf][0], qh[kf][1], qh[kf][2], qh[kf][3], qAddrBase + A_QH + kf * 32);
                ldsm_x4(ql[kf][0], ql[kf][1], ql[kf][2], ql[kf][3], qAddrBase + A_QL + kf * 32);
            }
        }

        const uint32_t stg = sb + A_STG + buf * A_STGSZ;

        // ---- S = Q K^T (scaled already), 16 x 64 per warp
        float sacc[8][4];
#pragma unroll
        for (int n = 0; n < 8; n++)
#pragma unroll
            for (int e = 0; e < 4; e++) sacc[n][e] = 0.0f;

#pragma unroll
        for (int j = 0; j < 4; j++) {
#pragma unroll
            for (int kf = 0; kf < 4; kf++) {
                const uint32_t a = stg + kOff + j * (16 * ATT_RB) + kf * 32;
                uint32_t h0, h1, h2, h3, l0, l1, l2, l3;
                ldsm_x4(h0, h1, h2, h3, a + A_KH);
                ldsm_x4(l0, l1, l2, l3, a + A_KL);
                uint32_t bh0[2] = {h0, h1}, bh1[2] = {h2, h3};
                uint32_t bl0[2] = {l0, l1}, bl1[2] = {l2, l3};
                mma_16816(sacc[2 * j],     qh[kf], bh0);
                mma_16816(sacc[2 * j],     ql[kf], bh0);
                mma_16816(sacc[2 * j],     qh[kf], bl0);
                mma_16816(sacc[2 * j + 1], qh[kf], bh1);
                mma_16816(sacc[2 * j + 1], ql[kf], bh1);
                mma_16816(sacc[2 * j + 1], qh[kf], bl1);
            }
        }

        // ---- online softmax (rows gid and gid+8; reduce over tig lanes)
#pragma unroll
        for (int r = 0; r < 2; r++) {
            float mt = -1e30f;
#pragma unroll
            for (int n = 0; n < 8; n++)
                mt = fmaxf(mt, fmaxf(sacc[n][2 * r], sacc[n][2 * r + 1]));
            mt = fmaxf(mt, __shfl_xor_sync(0xffffffffu, mt, 1));
            mt = fmaxf(mt, __shfl_xor_sync(0xffffffffu, mt, 2));
            const float mn    = fmaxf(m_r[r], mt);
            const float alpha = __expf(m_r[r] - mn);
            float rs = 0.0f;
#pragma unroll
            for (int n = 0; n < 8; n++) {
                const float p0 = __expf(sacc[n][2 * r] - mn);
                const float p1 = __expf(sacc[n][2 * r + 1] - mn);
                sacc[n][2 * r] = p0;
                sacc[n][2 * r + 1] = p1;
                rs += p0 + p1;
            }
            rs += __shfl_xor_sync(0xffffffffu, rs, 1);
            rs += __shfl_xor_sync(0xffffffffu, rs, 2);
            l_r[r] = l_r[r] * alpha + rs;
            m_r[r] = mn;
#pragma unroll
            for (int n = 0; n < 8; n++) {
                octx[n][2 * r]     *= alpha;
                octx[n][2 * r + 1] *= alpha;
            }
        }

        // ---- O += P V : P frags built from sacc in registers, V via ldsm.trans
#pragma unroll
        for (int kf = 0; kf < 4; kf++) {
            uint32_t pa_h[4], pa_l[4];
#pragma unroll
            for (int idx = 0; idx < 4; idx++) {
                const int n  = 2 * kf + (idx >> 1);
                const int e0 = (idx & 1) * 2;
                split_pack2(sacc[n][e0], sacc[n][e0 + 1], pa_h[idx], pa_l[idx]);
            }
#pragma unroll
            for (int j = 0; j < 4; j++) {
                const uint32_t a = stg + vOff + kf * (16 * ATT_RB) + j * 32;
                uint32_t h0, h1, h2, h3, l0, l1, l2, l3;
                ldsm_x4_t(h0, h1, h2, h3, a + A_VH);
                ldsm_x4_t(l0, l1, l2, l3, a + A_VL);
                uint32_t bh0[2] = {h0, h1}, bh1[2] = {h2, h3};
                uint32_t bl0[2] = {l0, l1}, bl1[2] = {l2, l3};
                mma_16816(octx[2 * j],     pa_h, bh0);
                mma_16816(octx[2 * j],     pa_l, bh0);
                mma_16816(octx[2 * j],     pa_h, bl0);
                mma_16816(octx[2 * j + 1], pa_h, bh1);
                mma_16816(octx[2 * j + 1], pa_l, bh1);
                mma_16816(octx[2 * j + 1], pa_h, bl1);
            }
        }
        __syncthreads();   // protect stage buffers before next issue
    }

    // ---- epilogue: normalize, split hi/lo, write ctx bf16
    const float inv0 = 1.0f / l_r[0];
    const float inv1 = 1.0f / l_r[1];
    const int qrow = q0 + 16 * wid + gid;
#pragma unroll
    for (int n = 0; n < 8; n++) {
        const int col = 8 * n + 2 * tig;
        uint32_t hp, lp;
        const size_t o0 = ((size_t)bh * SEQ + qrow) * DK + col;
        split_pack2(octx[n][0] * inv0, octx[n][1] * inv0, hp, lp);
        *(uint32_t*)(g_Chi + o0) = hp;  *(uint32_t*)(g_Clo + o0) = lp;
        const size_t o1 = ((size_t)bh * SEQ + qrow + 8) * DK + col;
        split_pack2(octx[n][2] * inv1, octx[n][3] * inv1, hp, lp);
        *(uint32_t*)(g_Chi + o1) = hp;  *(uint32_t*)(g_Clo + o1) = lp;
    }
}

// ---------------------------------------------------------------------------
extern "C" void kernel_launch(void* const* d_in, const int* in_sizes, int n_in,
                              void* d_out, int out_size)
{
    (void)in_sizes; (void)n_in; (void)out_size;
    const float* Q  = (const float*)d_in[0];
    const float* K  = (const float*)d_in[1];
    const float* V  = (const float*)d_in[2];
    const float* Wq = (const float*)d_in[3];
    const float* bq = (const float*)d_in[4];
    const float* Wk = (const float*)d_in[5];
    const float* bk = (const float*)d_in[6];
    const float* Wv = (const float*)d_in[7];
    const float* bv = (const float*)d_in[8];
    const float* Wo = (const float*)d_in[9];
    const float* bo = (const float*)d_in[10];
    float* Out = (float*)d_out;

    cudaFuncSetAttribute((const void*)gemm_mma<true>,
                         cudaFuncAttributeMaxDynamicSharedMemorySize, GSMEM_TOTAL);
    cudaFuncSetAttribute((const void*)gemm_mma<false>,
                         cudaFuncAttributeMaxDynamicSharedMemorySize, GSMEM_TOTAL);
    cudaFuncSetAttribute((const void*)attn_mma,
                         cudaFuncAttributeMaxDynamicSharedMemorySize, ATT_SMEM);

    const int nA4 = (M_TOTAL * D_MODEL) / 4;
    const int nW4 = (D_MODEL * D_MODEL) / 4;

    // 1) split-convert inputs + weights
    cvt_split_kernel<<<nA4 / 256, 256>>>(Q, 0, nA4);
    cvt_split_kernel<<<nA4 / 256, 256>>>(K, 1, nA4);
    cvt_split_kernel<<<nA4 / 256, 256>>>(V, 2, nA4);
    cvt_split_kernel<<<nW4 / 256, 256>>>(Wo, 3, nW4);
    prep_w_kernel<<<dim3(D_MODEL / 64, NHEADS, 3), 256>>>(Wq, Wk, Wv);

    // 2) QKV projections -> bf16 hi/lo heads (Q pre-scaled by 1/8)
    gemm_mma<true><<<dim3(D_MODEL / 128, M_TOTAL / 128, 3), 256, GSMEM_TOTAL>>>(
        bq, bk, bv, bo, Out);

    // 3) HMMA flash attention -> ctx hi/lo bf16
    attn_mma<<<dim3(SEQ / 128, BATCH * NHEADS), 256, ATT_SMEM>>>();

    // 4) output projection
    gemm_mma<false><<<dim3(D_MODEL / 128, M_TOTAL / 128, 1), 256, GSMEM_TOTAL>>>(
        bq, bk, bv, bo, Out);
}